// round 3
// baseline (speedup 1.0000x reference)
#include <cuda_runtime.h>

// LSTM1: B=4096, T=2048, I=6, H=2. One thread per sequence; recurrence in
// registers with packed f32x2 FMAs. Sigmoid input-scale (0.5) pre-folded into
// i/f/o weights+biases. Double buffer via unroll-2 constant indexing (no reg
// rotation MOVs). Fused MLP head.

#define B_DIM 4096
#define T_DIM 2048
#define I_DIM 6

typedef unsigned long long ull;

__device__ __forceinline__ ull pack2(float lo, float hi) {
    ull r; asm("mov.b64 %0, {%1, %2};" : "=l"(r) : "f"(lo), "f"(hi)); return r;
}
__device__ __forceinline__ void unpack2(ull v, float& lo, float& hi) {
    asm("mov.b64 {%0, %1}, %2;" : "=f"(lo), "=f"(hi) : "l"(v));
}
__device__ __forceinline__ ull fma2(ull a, ull b, ull c) {
    ull d; asm("fma.rn.f32x2 %0, %1, %2, %3;" : "=l"(d) : "l"(a), "l"(b), "l"(c)); return d;
}
__device__ __forceinline__ ull mul2(ull a, ull b) {
    ull d; asm("mul.rn.f32x2 %0, %1, %2;" : "=l"(d) : "l"(a), "l"(b)); return d;
}
__device__ __forceinline__ float tanh_ap(float x) {
    float y; asm("tanh.approx.f32 %0, %1;" : "=f"(y) : "f"(x)); return y;
}
__device__ __forceinline__ ull tanh2(ull x) {
    float a, b; unpack2(x, a, b);
    return pack2(tanh_ap(a), tanh_ap(b));
}

// One LSTM step. Gate pairs p: 0=i, 1=f, 2=g, 3=o (PyTorch order along 4H).
// Weights/biases for p in {0,1,3} are PRE-SCALED by 0.5, so
// sigmoid(pre) = 0.5*tanh(0.5*pre)+0.5 = fma2(tanh2(z), half, half).
__device__ __forceinline__ void lstm_step(
    float x0, float x1, float x2, float x3, float x4, float x5,
    const ull (&wp)[4][6], const ull (&whp0)[4], const ull (&whp1)[4],
    const ull (&bp)[4], ull halfc,
    ull& cpack, ull& hpack)
{
    float h0, h1; unpack2(hpack, h0, h1);
    const ull hb0 = pack2(h0, h0), hb1 = pack2(h1, h1);

    const ull xb0 = pack2(x0, x0), xb1 = pack2(x1, x1), xb2 = pack2(x2, x2),
              xb3 = pack2(x3, x3), xb4 = pack2(x4, x4), xb5 = pack2(x5, x5);

    ull g0 = bp[0], g1 = bp[1], g2 = bp[2], g3 = bp[3];
    // h terms first (shortest path from previous step's h).
    g0 = fma2(hb0, whp0[0], g0); g0 = fma2(hb1, whp1[0], g0);
    g1 = fma2(hb0, whp0[1], g1); g1 = fma2(hb1, whp1[1], g1);
    g2 = fma2(hb0, whp0[2], g2); g2 = fma2(hb1, whp1[2], g2);
    g3 = fma2(hb0, whp0[3], g3); g3 = fma2(hb1, whp1[3], g3);
#pragma unroll
    for (int i = 0; i < 6; i++) {
        const ull xb = (i == 0) ? xb0 : (i == 1) ? xb1 : (i == 2) ? xb2
                     : (i == 3) ? xb3 : (i == 4) ? xb4 : xb5;
        g0 = fma2(xb, wp[0][i], g0);
        g1 = fma2(xb, wp[1][i], g1);
        g2 = fma2(xb, wp[2][i], g2);
        g3 = fma2(xb, wp[3][i], g3);
    }

    const ull ig = fma2(tanh2(g0), halfc, halfc);
    const ull fg = fma2(tanh2(g1), halfc, halfc);
    const ull gg = tanh2(g2);
    const ull og = fma2(tanh2(g3), halfc, halfc);

    cpack = fma2(fg, cpack, mul2(ig, gg));
    hpack = mul2(og, tanh2(cpack));
}

__global__ void __launch_bounds__(32, 1) lstm_fused_kernel(
    const float* __restrict__ x,
    const float* __restrict__ w_ih, const float* __restrict__ w_hh,
    const float* __restrict__ b_ih, const float* __restrict__ b_hh,
    const float* __restrict__ fc1_w, const float* __restrict__ fc1_b,
    const float* __restrict__ fc_w, const float* __restrict__ fc_b,
    float* __restrict__ out)
{
    const int b = blockIdx.x * 32 + threadIdx.x;
    if (b >= B_DIM) return;

    // Pack weights; pre-scale sigmoid gates (i=0, f=1, o=3) by 0.5.
    ull wp[4][6], whp0[4], whp1[4], bp[4];
#pragma unroll
    for (int p = 0; p < 4; p++) {
        const float s = (p == 2) ? 1.0f : 0.5f;
#pragma unroll
        for (int i = 0; i < 6; i++)
            wp[p][i] = pack2(s * w_ih[(2 * p) * 6 + i], s * w_ih[(2 * p + 1) * 6 + i]);
        whp0[p] = pack2(s * w_hh[(2 * p) * 2 + 0], s * w_hh[(2 * p + 1) * 2 + 0]);
        whp1[p] = pack2(s * w_hh[(2 * p) * 2 + 1], s * w_hh[(2 * p + 1) * 2 + 1]);
        bp[p]   = pack2(s * (b_ih[2 * p]     + b_hh[2 * p]),
                        s * (b_ih[2 * p + 1] + b_hh[2 * p + 1]));
    }
    const ull halfc = pack2(0.5f, 0.5f);

    const float4* xb4 = (const float4*)(x + (size_t)b * (T_DIM * I_DIM));
    ull cpack = pack2(0.f, 0.f);
    ull hpack = pack2(0.f, 0.f);

    // 4 steps per chunk = 24 floats = 6 float4. Double buffer with
    // compile-time buffer index (unroll 2) -> zero rotation MOVs.
    const int NCH = T_DIM / 4;  // 512
    float4 buf[2][6];
#pragma unroll
    for (int i = 0; i < 6; i++) buf[0][i] = xb4[i];

#pragma unroll 2
    for (int k = 0; k < NCH; k++) {
        const int cur = k & 1, nxt = cur ^ 1;
        const int kn = (k + 1 < NCH) ? (k + 1) : k;
        const float4* nb = xb4 + 6 * kn;
#pragma unroll
        for (int i = 0; i < 6; i++) buf[nxt][i] = nb[i];
        if (k + 16 < NCH)
            asm volatile("prefetch.global.L2 [%0];" :: "l"(xb4 + 6 * (k + 16)));

        const float4 ca = buf[cur][0], cb = buf[cur][1], cc = buf[cur][2],
                     cd = buf[cur][3], ce = buf[cur][4], cf = buf[cur][5];
        lstm_step(ca.x, ca.y, ca.z, ca.w, cb.x, cb.y,
                  wp, whp0, whp1, bp, halfc, cpack, hpack);
        lstm_step(cb.z, cb.w, cc.x, cc.y, cc.z, cc.w,
                  wp, whp0, whp1, bp, halfc, cpack, hpack);
        lstm_step(cd.x, cd.y, cd.z, cd.w, ce.x, ce.y,
                  wp, whp0, whp1, bp, halfc, cpack, hpack);
        lstm_step(ce.z, ce.w, cf.x, cf.y, cf.z, cf.w,
                  wp, whp0, whp1, bp, halfc, cpack, hpack);
    }

    // Head: relu(h) -> fc1[128,2]+b1, relu -> fc[1,128]+b
    float h0, h1; unpack2(hpack, h0, h1);
    const float r0 = fmaxf(h0, 0.f), r1 = fmaxf(h1, 0.f);
    float acc = fc_b[0];
#pragma unroll 8
    for (int j = 0; j < 128; j++) {
        const float2 w = ((const float2*)fc1_w)[j];
        float v = fmaf(w.x, r0, fmaf(w.y, r1, fc1_b[j]));
        v = fmaxf(v, 0.f);
        acc = fmaf(v, fc_w[j], acc);
    }
    out[b] = acc;
}

extern "C" void kernel_launch(void* const* d_in, const int* in_sizes, int n_in,
                              void* d_out, int out_size) {
    (void)in_sizes; (void)n_in; (void)out_size;
    lstm_fused_kernel<<<B_DIM / 32, 32>>>(
        (const float*)d_in[0],  // x
        (const float*)d_in[1],  // w_ih
        (const float*)d_in[2],  // w_hh
        (const float*)d_in[3],  // b_ih
        (const float*)d_in[4],  // b_hh
        (const float*)d_in[5],  // fc1_w
        (const float*)d_in[6],  // fc1_b
        (const float*)d_in[7],  // fc_w
        (const float*)d_in[8],  // fc_b
        (float*)d_out);
}

// round 4
// speedup vs baseline: 1.0273x; 1.0273x over previous
#include <cuda_runtime.h>

// LSTM1: B=4096, T=2048, I=6, H=2. One thread per sequence, plain scalar fp32
// (fma.rn.f32x2 is sm_103a-only; on sm_100a it is emulated at 2x cost plus
// pack/unpack MOVs -- measured as ~230 issues/step vs ~90 scalar).
// Sigmoid input-scale 0.5 pre-folded into i/f/o weights+biases:
//   sigmoid(z) = 0.5*tanh(0.5*z)+0.5, with the 0.5*z folded into the weights.
// Gate accumulation order: bias -> 6 x-terms -> 2 h-terms LAST (keeps the
// recurrence-critical path from h to the activations at 2 FMAs).

#define B_DIM 4096
#define T_DIM 2048
#define I_DIM 6

__device__ __forceinline__ float tanh_ap(float x) {
    float y; asm("tanh.approx.f32 %0, %1;" : "=f"(y) : "f"(x)); return y;
}

// One LSTM step. Rows r=0..7 map to gates (i0,i1,f0,f1,g0,g1,o0,o1) after the
// host-order remap below; w[r][0..5]=x weights, wh[r][0..1]=h weights, bs[r]=bias.
__device__ __forceinline__ void lstm_step(
    float x0, float x1, float x2, float x3, float x4, float x5,
    const float (&w)[8][6], const float (&wh)[8][2], const float (&bs)[8],
    float& c0, float& c1, float& h0, float& h1)
{
    float g[8];
#pragma unroll
    for (int r = 0; r < 8; r++) {
        float a = bs[r];
        a = fmaf(x0, w[r][0], a);
        a = fmaf(x1, w[r][1], a);
        a = fmaf(x2, w[r][2], a);
        a = fmaf(x3, w[r][3], a);
        a = fmaf(x4, w[r][4], a);
        a = fmaf(x5, w[r][5], a);
        // h terms LAST: shortest dependency path from previous step's h.
        a = fmaf(h0, wh[r][0], a);
        a = fmaf(h1, wh[r][1], a);
        g[r] = a;
    }
    // rows 0,1 = i; 2,3 = f; 4,5 = g; 6,7 = o
    const float i0 = fmaf(tanh_ap(g[0]), 0.5f, 0.5f);
    const float i1 = fmaf(tanh_ap(g[1]), 0.5f, 0.5f);
    const float f0 = fmaf(tanh_ap(g[2]), 0.5f, 0.5f);
    const float f1 = fmaf(tanh_ap(g[3]), 0.5f, 0.5f);
    const float gg0 = tanh_ap(g[4]);
    const float gg1 = tanh_ap(g[5]);
    const float o0 = fmaf(tanh_ap(g[6]), 0.5f, 0.5f);
    const float o1 = fmaf(tanh_ap(g[7]), 0.5f, 0.5f);

    c0 = fmaf(f0, c0, i0 * gg0);
    c1 = fmaf(f1, c1, i1 * gg1);
    h0 = o0 * tanh_ap(c0);
    h1 = o1 * tanh_ap(c1);
}

__global__ void __launch_bounds__(32, 1) lstm_fused_kernel(
    const float* __restrict__ x,
    const float* __restrict__ w_ih, const float* __restrict__ w_hh,
    const float* __restrict__ b_ih, const float* __restrict__ b_hh,
    const float* __restrict__ fc1_w, const float* __restrict__ fc1_b,
    const float* __restrict__ fc_w, const float* __restrict__ fc_b,
    float* __restrict__ out)
{
    const int b = blockIdx.x * 32 + threadIdx.x;
    if (b >= B_DIM) return;

    // Load weights; rows 0..7 = (i0,i1,f0,f1,g0,g1,o0,o1) in source order
    // already (PyTorch gate order i,f,g,o along 4H with H=2).
    // Pre-scale sigmoid rows (i,f,o = rows 0-3,6-7) by 0.5.
    float w[8][6], wh[8][2], bs[8];
#pragma unroll
    for (int r = 0; r < 8; r++) {
        const float s = (r == 4 || r == 5) ? 1.0f : 0.5f;
#pragma unroll
        for (int i = 0; i < 6; i++) w[r][i] = s * w_ih[r * 6 + i];
        wh[r][0] = s * w_hh[r * 2 + 0];
        wh[r][1] = s * w_hh[r * 2 + 1];
        bs[r] = s * (b_ih[r] + b_hh[r]);
    }

    const float4* xb4 = (const float4*)(x + (size_t)b * (T_DIM * I_DIM));
    float c0 = 0.f, c1 = 0.f, h0 = 0.f, h1 = 0.f;

    // 4 steps per chunk = 24 floats = 6 float4. Double buffer with
    // compile-time buffer index (unroll 2) -> no rotation MOVs.
    const int NCH = T_DIM / 4;  // 512
    float4 buf[2][6];
#pragma unroll
    for (int i = 0; i < 6; i++) buf[0][i] = xb4[i];

#pragma unroll 2
    for (int k = 0; k < NCH; k++) {
        const int cur = k & 1, nxt = cur ^ 1;
        const int kn = (k + 1 < NCH) ? (k + 1) : k;
        const float4* nb = xb4 + 6 * kn;
#pragma unroll
        for (int i = 0; i < 6; i++) buf[nxt][i] = nb[i];
        if (k + 16 < NCH)
            asm volatile("prefetch.global.L2 [%0];" :: "l"(xb4 + 6 * (k + 16)));

        const float4 ca = buf[cur][0], cb = buf[cur][1], cc = buf[cur][2],
                     cd = buf[cur][3], ce = buf[cur][4], cf = buf[cur][5];
        lstm_step(ca.x, ca.y, ca.z, ca.w, cb.x, cb.y, w, wh, bs, c0, c1, h0, h1);
        lstm_step(cb.z, cb.w, cc.x, cc.y, cc.z, cc.w, w, wh, bs, c0, c1, h0, h1);
        lstm_step(cd.x, cd.y, cd.z, cd.w, ce.x, ce.y, w, wh, bs, c0, c1, h0, h1);
        lstm_step(ce.z, ce.w, cf.x, cf.y, cf.z, cf.w, w, wh, bs, c0, c1, h0, h1);
    }

    // Head: relu(h) -> fc1[128,2]+b1, relu -> fc[1,128]+b
    const float r0 = fmaxf(h0, 0.f), r1 = fmaxf(h1, 0.f);
    float acc = fc_b[0];
#pragma unroll 8
    for (int j = 0; j < 128; j++) {
        const float2 wv = ((const float2*)fc1_w)[j];
        float v = fmaf(wv.x, r0, fmaf(wv.y, r1, fc1_b[j]));
        v = fmaxf(v, 0.f);
        acc = fmaf(v, fc_w[j], acc);
    }
    out[b] = acc;
}

extern "C" void kernel_launch(void* const* d_in, const int* in_sizes, int n_in,
                              void* d_out, int out_size) {
    (void)in_sizes; (void)n_in; (void)out_size;
    lstm_fused_kernel<<<B_DIM / 32, 32>>>(
        (const float*)d_in[0],  // x
        (const float*)d_in[1],  // w_ih
        (const float*)d_in[2],  // w_hh
        (const float*)d_in[3],  // b_ih
        (const float*)d_in[4],  // b_hh
        (const float*)d_in[5],  // fc1_w
        (const float*)d_in[6],  // fc1_b
        (const float*)d_in[7],  // fc_w
        (const float*)d_in[8],  // fc_b
        (float*)d_out);
}

// round 5
// speedup vs baseline: 1.4050x; 1.3677x over previous
#include <cuda_runtime.h>

// LSTM1: B=4096, T=2048, I=6, H=2. TWO threads per sequence: thread parity p
// owns hidden lane p (gate rows i_p, f_p, g_p, o_p, state c_p, h_p).
// Halves the per-warp FMA-pipe occupancy (rt_SMSP=2 made 76 FFMA/step a
// 152-cycle floor with 1 thread/seq). The only cross-thread dependency is h:
// one shfl.xor(1) per step. Peer/own h-weight columns are swapped at load per
// parity so no selects appear in the loop.
// Sigmoid input-scale 0.5 pre-folded into i/f/o weights+biases.

#define B_DIM 4096
#define T_DIM 2048
#define I_DIM 6

__device__ __forceinline__ float tanh_ap(float x) {
    float y; asm("tanh.approx.f32 %0, %1;" : "=f"(y) : "f"(x)); return y;
}

// One step for one h-lane. r = 0:i, 1:f, 2:g, 3:o.
// w[r][0..5]: x weights; whO[r]: own-h weight; whP[r]: peer-h weight.
__device__ __forceinline__ void lstm_step_half(
    float x0, float x1, float x2, float x3, float x4, float x5,
    const float (&w)[4][6], const float (&whO)[4], const float (&whP)[4],
    const float (&bs)[4],
    float& c, float& h_own, float& h_peer)
{
    float g[4];
#pragma unroll
    for (int r = 0; r < 4; r++) {
        float a = bs[r];
        a = fmaf(x0, w[r][0], a);
        a = fmaf(x1, w[r][1], a);
        a = fmaf(x2, w[r][2], a);
        a = fmaf(x3, w[r][3], a);
        a = fmaf(x4, w[r][4], a);
        a = fmaf(x5, w[r][5], a);
        // h terms LAST (shortest path from previous step's h / shfl result).
        a = fmaf(h_own, whO[r], a);
        a = fmaf(h_peer, whP[r], a);
        g[r] = a;
    }
    const float ig = fmaf(tanh_ap(g[0]), 0.5f, 0.5f);
    const float fg = fmaf(tanh_ap(g[1]), 0.5f, 0.5f);
    const float gg = tanh_ap(g[2]);
    const float og = fmaf(tanh_ap(g[3]), 0.5f, 0.5f);

    c = fmaf(fg, c, ig * gg);
    h_own = og * tanh_ap(c);
    h_peer = __shfl_xor_sync(0xFFFFFFFFu, h_own, 1);
}

__global__ void __launch_bounds__(64, 1) lstm_fused_kernel(
    const float* __restrict__ x,
    const float* __restrict__ w_ih, const float* __restrict__ w_hh,
    const float* __restrict__ b_ih, const float* __restrict__ b_hh,
    const float* __restrict__ fc1_w, const float* __restrict__ fc1_b,
    const float* __restrict__ fc_w, const float* __restrict__ fc_b,
    float* __restrict__ out)
{
    const int tid = blockIdx.x * 64 + threadIdx.x;   // 8192 threads
    const int seq = tid >> 1;                        // sequence index
    const int p = tid & 1;                           // h-lane owned

    // Gate rows for lane p in PyTorch i,f,g,o order (H=2):
    // i -> row p, f -> row 2+p, g -> row 4+p, o -> row 6+p.
    float w[4][6], whO[4], whP[4], bs[4];
#pragma unroll
    for (int r = 0; r < 4; r++) {
        const int gr = 2 * r + p;                    // global gate row
        const float s = (r == 2) ? 1.0f : 0.5f;      // g-gate unscaled
#pragma unroll
        for (int i = 0; i < 6; i++) w[r][i] = s * w_ih[gr * 6 + i];
        whO[r] = s * w_hh[gr * 2 + p];               // multiplies own h
        whP[r] = s * w_hh[gr * 2 + (1 - p)];         // multiplies peer h
        bs[r] = s * (b_ih[gr] + b_hh[gr]);
    }

    const float4* xb4 = (const float4*)(x + (size_t)seq * (T_DIM * I_DIM));
    float c = 0.f, h_own = 0.f, h_peer = 0.f;

    // 4 steps per chunk = 24 floats = 6 float4 (both pair threads load the
    // same addresses; coalescer merges). Double buffer, compile-time index.
    const int NCH = T_DIM / 4;  // 512
    float4 buf[2][6];
#pragma unroll
    for (int i = 0; i < 6; i++) buf[0][i] = xb4[i];

#pragma unroll 2
    for (int k = 0; k < NCH; k++) {
        const int cur = k & 1, nxt = cur ^ 1;
        const int kn = (k + 1 < NCH) ? (k + 1) : k;
        const float4* nb = xb4 + 6 * kn;
#pragma unroll
        for (int i = 0; i < 6; i++) buf[nxt][i] = nb[i];
        if (k + 16 < NCH)
            asm volatile("prefetch.global.L2 [%0];" :: "l"(xb4 + 6 * (k + 16)));

        const float4 ca = buf[cur][0], cb = buf[cur][1], cc = buf[cur][2],
                     cd = buf[cur][3], ce = buf[cur][4], cf = buf[cur][5];
        lstm_step_half(ca.x, ca.y, ca.z, ca.w, cb.x, cb.y,
                       w, whO, whP, bs, c, h_own, h_peer);
        lstm_step_half(cb.z, cb.w, cc.x, cc.y, cc.z, cc.w,
                       w, whO, whP, bs, c, h_own, h_peer);
        lstm_step_half(cd.x, cd.y, cd.z, cd.w, ce.x, ce.y,
                       w, whO, whP, bs, c, h_own, h_peer);
        lstm_step_half(ce.z, ce.w, cf.x, cf.y, cf.z, cf.w,
                       w, whO, whP, bs, c, h_own, h_peer);
    }

    // Head on even threads only: they hold h0 = h_own, h1 = h_peer.
    if (p == 0) {
        const float r0 = fmaxf(h_own, 0.f), r1 = fmaxf(h_peer, 0.f);
        float acc = fc_b[0];
#pragma unroll 8
        for (int j = 0; j < 128; j++) {
            const float2 wv = ((const float2*)fc1_w)[j];
            float v = fmaf(wv.x, r0, fmaf(wv.y, r1, fc1_b[j]));
            v = fmaxf(v, 0.f);
            acc = fmaf(v, fc_w[j], acc);
        }
        out[seq] = acc;
    }
}

extern "C" void kernel_launch(void* const* d_in, const int* in_sizes, int n_in,
                              void* d_out, int out_size) {
    (void)in_sizes; (void)n_in; (void)out_size;
    lstm_fused_kernel<<<(2 * B_DIM) / 64, 64>>>(
        (const float*)d_in[0],  // x
        (const float*)d_in[1],  // w_ih
        (const float*)d_in[2],  // w_hh
        (const float*)d_in[3],  // b_ih
        (const float*)d_in[4],  // b_hh
        (const float*)d_in[5],  // fc1_w
        (const float*)d_in[6],  // fc1_b
        (const float*)d_in[7],  // fc_w
        (const float*)d_in[8],  // fc_b
        (float*)d_out);
}